// round 10
// baseline (speedup 1.0000x reference)
#include <cuda_runtime.h>
#include <stdint.h>

#define EMB   1024
#define NH    16
#define HD    64
#define BATCH 4
#define SEQ   2048
#define MROWS (BATCH*SEQ)   // 8192
#define KDIM  EMB           // 1024
#define WSZ   (EMB*EMB)     // 1M floats per weight

// ---------------- scratch (static __device__, allocation-guard safe) ----------
__device__ float g_q  [(size_t)BATCH*NH*SEQ*HD];  // [B,H,S,D] (tf32, q pre-scaled)
__device__ float g_k  [(size_t)BATCH*NH*SEQ*HD];
__device__ float g_v  [(size_t)BATCH*NH*SEQ*HD];
__device__ float g_ao [(size_t)MROWS*EMB];        // attention out (tf32), [B,S,E]
__device__ float g_x32[(size_t)MROWS*EMB];        // tf32-rounded x
__device__ float g_wt [(size_t)4*WSZ];            // tf32-rounded wq,wk,wv,wo

// ---------------- TF32 / MMA / LDSM / cp.async helpers --------------------------
__device__ __forceinline__ uint32_t f2tf32(float x) {
    uint32_t r;
    asm("cvt.rna.tf32.f32 %0, %1;" : "=r"(r) : "f"(x));
    return r;
}
__device__ __forceinline__ float f2tf32f(float x) {
    return __uint_as_float(f2tf32(x));
}

__device__ __forceinline__ void mma_tf32(float& d0, float& d1, float& d2, float& d3,
                                         uint32_t a0, uint32_t a1, uint32_t a2, uint32_t a3,
                                         uint32_t b0, uint32_t b1)
{
    asm volatile(
        "mma.sync.aligned.m16n8k8.row.col.f32.tf32.tf32.f32 "
        "{%0,%1,%2,%3}, {%4,%5,%6,%7}, {%8,%9}, {%0,%1,%2,%3};"
        : "+f"(d0), "+f"(d1), "+f"(d2), "+f"(d3)
        : "r"(a0), "r"(a1), "r"(a2), "r"(a3), "r"(b0), "r"(b1));
}

__device__ __forceinline__ void ldsm_x4(uint32_t* r, uint32_t addr) {
    asm volatile("ldmatrix.sync.aligned.m8n8.x4.shared.b16 {%0,%1,%2,%3}, [%4];"
                 : "=r"(r[0]), "=r"(r[1]), "=r"(r[2]), "=r"(r[3]) : "r"(addr));
}
__device__ __forceinline__ void ldsm_x2(uint32_t* r, uint32_t addr) {
    asm volatile("ldmatrix.sync.aligned.m8n8.x2.shared.b16 {%0,%1}, [%2];"
                 : "=r"(r[0]), "=r"(r[1]) : "r"(addr));
}

__device__ __forceinline__ void cp16(uint32_t dst, const float* src) {
    asm volatile("cp.async.cg.shared.global [%0], [%1], 16;" :: "r"(dst), "l"(src));
}
#define CP_COMMIT() asm volatile("cp.async.commit_group;")
#define CP_WAIT(n)  asm volatile("cp.async.wait_group %0;" :: "n"(n))

// ---------------- pre-convert kernels (memory-bound, ~15us total) ---------------
__global__ void cvt_x_kernel(const float4* __restrict__ src, float4* __restrict__ dst,
                             int n4)
{
    for (int i = blockIdx.x * blockDim.x + threadIdx.x; i < n4;
         i += gridDim.x * blockDim.x) {
        float4 t = src[i];
        dst[i] = make_float4(f2tf32f(t.x), f2tf32f(t.y), f2tf32f(t.z), f2tf32f(t.w));
    }
}

__global__ void cvt_w_kernel(const float4* __restrict__ wq, const float4* __restrict__ wk,
                             const float4* __restrict__ wv, const float4* __restrict__ wo,
                             float4* __restrict__ dst)
{
    const int z = blockIdx.z;
    const float4* src = (z == 0) ? wq : (z == 1) ? wk : (z == 2) ? wv : wo;
    float4* d = dst + (size_t)z * (WSZ / 4);
    for (int i = blockIdx.x * blockDim.x + threadIdx.x; i < WSZ / 4;
         i += gridDim.x * blockDim.x) {
        float4 t = src[i];
        d[i] = make_float4(f2tf32f(t.x), f2tf32f(t.y), f2tf32f(t.z), f2tf32f(t.w));
    }
}

// ---------------- TF32 tensor-core GEMM (cp.async 3-stage, ldmatrix) ------------
// C[M,N] = A[M,K] @ W[N,K]^T.  A/W already tf32-rounded in gmem.
// Block 128x128x32, 8 warps (2x4), warp tile 64x32. Row-major smem, stride 36.
#define BM 128
#define BN 128
#define BK 32
#define GST 36
#define STAGE_FLOATS (2*BM*GST)            // As + Ws per stage = 9216
#define STAGE_BYTES  (STAGE_FLOATS*4)      // 36864
#define NSTAGE 3
#define GSMEM_BYTES (NSTAGE*STAGE_BYTES)   // 110592

template<bool SPLIT, bool CVTOUT>
__device__ __forceinline__ void gemm_body(const float* __restrict__ A,
                                          const float* __restrict__ W,
                                          float* __restrict__ C,
                                          float* __restrict__ sm,
                                          float escale)
{
    const int tid    = threadIdx.x;
    const int lane   = tid & 31;
    const int warp   = tid >> 5;
    const int warp_m = warp >> 2;           // 0..1
    const int warp_n = warp & 3;            // 0..3
    const int m0     = blockIdx.y * BM;
    const int n0     = blockIdx.x * BN;
    const int mw     = warp_m * 64;
    const int nw     = warp_n * 32;

    const uint32_t sbase = (uint32_t)__cvta_generic_to_shared(sm);

    // per-lane ldmatrix byte offsets within a stage
    uint32_t aoff[4], boff[4];
    #pragma unroll
    for (int mi = 0; mi < 4; mi++)
        aoff[mi] = (uint32_t)(((mw + mi * 16 + (lane & 15)) * GST + 4 * (lane >> 4)) * 4);
    #pragma unroll
    for (int ni = 0; ni < 4; ni++)
        boff[ni] = (uint32_t)(((nw + ni * 8 + (lane & 7)) * GST + 4 * ((lane >> 3) & 1)
                               + BM * GST) * 4);

    const int srow = tid >> 3;              // 0..31 (+32p)
    const int scol = (tid & 7) * 4;         // 0,4,..,28

    float acc[4][4][4];
    #pragma unroll
    for (int i = 0; i < 4; i++)
        #pragma unroll
        for (int j = 0; j < 4; j++)
            #pragma unroll
            for (int c = 0; c < 4; c++) acc[i][j][c] = 0.f;

    // prologue: slabs 0,1 -> stages 0,1
    #pragma unroll
    for (int s = 0; s < 2; s++) {
        const uint32_t sd = sbase + s * STAGE_BYTES;
        #pragma unroll
        for (int p = 0; p < 4; p++) {
            const int row = srow + p * 32;
            cp16(sd + (row * GST + scol) * 4,
                 A + (size_t)(m0 + row) * KDIM + s * BK + scol);
            cp16(sd + (BM * GST + row * GST + scol) * 4,
                 W + (size_t)(n0 + row) * KDIM + s * BK + scol);
        }
        CP_COMMIT();
    }

    const int NIT = KDIM / BK;   // 32
    for (int it = 0; it < NIT; it++) {
        CP_WAIT(1);              // group 'it' complete (per-thread)
        __syncthreads();         // visible to all; also fences stage reuse

        // issue slab it+2 into stage (it+2)%3 (overlaps compute below)
        if (it + 2 < NIT) {
            const uint32_t sd = sbase + ((it + 2) % NSTAGE) * STAGE_BYTES;
            const int kk = (it + 2) * BK;
            #pragma unroll
            for (int p = 0; p < 4; p++) {
                const int row = srow + p * 32;
                cp16(sd + (row * GST + scol) * 4,
                     A + (size_t)(m0 + row) * KDIM + kk + scol);
                cp16(sd + (BM * GST + row * GST + scol) * 4,
                     W + (size_t)(n0 + row) * KDIM + kk + scol);
            }
        }
        CP_COMMIT();             // always: keeps one group per iteration

        // compute from stage it%3
        const uint32_t bufo = (uint32_t)((it % NSTAGE) * STAGE_BYTES);
        #pragma unroll
        for (int kb = 0; kb < 4; kb++) {
            const uint32_t ko = bufo + kb * 32;
            uint32_t af[4][4];
            #pragma unroll
            for (int mi = 0; mi < 4; mi++)
                ldsm_x4(af[mi], sbase + ko + aoff[mi]);
            uint32_t bf[4][2];
            #pragma unroll
            for (int ni = 0; ni < 4; ni++)
                ldsm_x2(bf[ni], sbase + ko + boff[ni]);
            #pragma unroll
            for (int mi = 0; mi < 4; mi++)
                #pragma unroll
                for (int ni = 0; ni < 4; ni++)
                    mma_tf32(acc[mi][ni][0], acc[mi][ni][1], acc[mi][ni][2], acc[mi][ni][3],
                             af[mi][0], af[mi][1], af[mi][2], af[mi][3],
                             bf[ni][0], bf[ni][1]);
        }
        __syncthreads();
    }

    // ---- epilogue ----
    const int grp = lane >> 2;
    const int tig = lane & 3;
    #pragma unroll
    for (int mi = 0; mi < 4; mi++) {
        #pragma unroll
        for (int ni = 0; ni < 4; ni++) {
            const int row = m0 + mw + mi * 16 + grp;
            const int col = n0 + nw + ni * 8 + 2 * tig;
            #pragma unroll
            for (int half = 0; half < 2; half++) {
                const int m = row + half * 8;
                float v0 = acc[mi][ni][half * 2 + 0];
                float v1 = acc[mi][ni][half * 2 + 1];
                if (CVTOUT) { v0 = f2tf32f(v0 * escale); v1 = f2tf32f(v1 * escale); }
                size_t idx;
                if (SPLIT) {   // [B,H,S,D]
                    const int b = m >> 11, s = m & 2047, h = col >> 6, d = col & 63;
                    idx = ((size_t)(b * NH + h) * SEQ + s) * HD + d;
                } else {
                    idx = (size_t)m * EMB + col;
                }
                *(float2*)(C + idx) = make_float2(v0, v1);
            }
        }
    }
}

// fused QKV: gridDim.z = 3 selects weight/output; Q epilogue folds qscale
#define QSCALE (0.125f * 1.44269504088896f)   // 1/sqrt(64) * log2(e)

__global__ void __launch_bounds__(256)
qkv_gemm(const float* __restrict__ x32, const float* __restrict__ wt,
         float* __restrict__ pq, float* __restrict__ pk, float* __restrict__ pv)
{
    extern __shared__ __align__(16) float smg[];
    const int z = blockIdx.z;
    const float* W = wt + (size_t)z * WSZ;
    float*       C = (z == 0) ? pq : (z == 1) ? pk : pv;
    const float  e = (z == 0) ? QSCALE : 1.0f;
    gemm_body<true, true>(x32, W, C, smg, e);
}

__global__ void __launch_bounds__(256)
out_gemm(const float* __restrict__ A, const float* __restrict__ W,
         float* __restrict__ C)
{
    extern __shared__ __align__(16) float smg[];
    gemm_body<false, false>(A, W, C, smg, 1.0f);
}

// ---------------- tensor-core causal flash attention ---------------------------
// CTA: 128 q-rows of one (b,h). 8 warps x 16 q-rows. KV tiles of 64.
// Q/K/V arrive tf32-rounded (Q pre-scaled) -> staging is pure cp.async.
#define KST 68
#define VSTR 72
#define FLASH_SMEM_FLOATS (64*KST + 64*VSTR + 128*KST)
#define FLASH_SMEM_BYTES  (FLASH_SMEM_FLOATS*4 + 64*4)

__global__ void __launch_bounds__(256)
flash_tc(const float* __restrict__ Qg, const float* __restrict__ Kg,
         const float* __restrict__ Vg, const int* __restrict__ maskg,
         float* __restrict__ Og)
{
    extern __shared__ __align__(16) float sm[];
    float* Ks = sm;                    // [64][KST]
    float* Vs = Ks + 64 * KST;         // [64][VSTR]
    float* Ps = Vs + 64 * VSTR;        // [128][KST]  (Q staging, then P)
    int*   msk = (int*)(Ps + 128 * KST);

    const int bh   = blockIdx.x;
    const int b    = bh >> 4;
    const int h    = bh & 15;
    const int qt   = gridDim.y - 1 - blockIdx.y;   // heavy tiles first
    const int q0   = qt * 128;
    const int tid  = threadIdx.x;
    const int lane = tid & 31;
    const int warp = tid >> 5;
    const int grp  = lane >> 2;
    const int tig  = lane & 3;
    const int mw   = warp * 16;

    const uint32_t sbK = (uint32_t)__cvta_generic_to_shared(Ks);
    const uint32_t sbV = (uint32_t)__cvta_generic_to_shared(Vs);
    const uint32_t sbP = (uint32_t)__cvta_generic_to_shared(Ps);
    const uint32_t paoff = (uint32_t)(((mw + (lane & 15)) * KST + 4 * (lane >> 4)) * 4);
    const uint32_t kboff = (uint32_t)((((lane & 7)) * KST + 4 * ((lane >> 3) & 1)) * 4);

    // ---- stage Q tile [128 x 64] via cp.async (already scaled+rounded) ----
    #pragma unroll
    for (int p = 0; p < 8; p++) {
        const int idx = tid + p * 256;
        const int row = idx >> 4;
        const int col = (idx & 15) * 4;
        cp16(sbP + (uint32_t)((row * KST + col) * 4),
             Qg + ((size_t)bh * SEQ + q0 + row) * HD + col);
    }
    CP_COMMIT();
    CP_WAIT(0);
    __syncthreads();

    uint32_t qf[8][4];
    #pragma unroll
    for (int ks = 0; ks < 8; ks++)
        ldsm_x4(qf[ks], sbP + paoff + ks * 32);

    float o[8][4];
    #pragma unroll
    for (int nt = 0; nt < 8; nt++)
        #pragma unroll
        for (int c = 0; c < 4; c++) o[nt][c] = 0.f;
    float m0r = -1e30f, m1r = -1e30f, l0 = 0.f, l1 = 0.f;

    const int q_row0 = q0 + mw + grp;
    const int q_row1 = q_row0 + 8;
    const int* mrow  = maskg + b * SEQ;
    const int  ntile = 2 * qt + 2;

    for (int kt = 0; kt < ntile; kt++) {
        const int kv0 = kt * 64;
        __syncthreads();   // previous tile's Ks/Vs (and P/Q) reads complete

        // ---- stage K,V tiles via cp.async + load mask ----
        #pragma unroll
        for (int p = 0; p < 4; p++) {
            const int idx = tid + p * 256;
            const int row = idx >> 4;
            const int col = (idx & 15) * 4;
            cp16(sbK + (uint32_t)((row * KST + col) * 4),
                 Kg + ((size_t)bh * SEQ + kv0 + row) * HD + col);
            cp16(sbV + (uint32_t)((row * VSTR + col) * 4),
                 Vg + ((size_t)bh * SEQ + kv0 + row) * HD + col);
        }
        CP_COMMIT();
        int mv = 1;
        if (tid < 64) { mv = mrow[kv0 + tid]; msk[tid] = mv; }
        CP_WAIT(0);
        const int allv = __syncthreads_and(mv != 0);   // barrier + all-reduce

        // ---- S = Q @ K^T ----
        float s[8][4];
        #pragma unroll
        for (int nt = 0; nt < 8; nt++)
            #pragma unroll
            for (int c = 0; c < 4; c++) s[nt][c] = 0.f;

        #pragma unroll
        for (int ks = 0; ks < 8; ks++) {
            #pragma unroll
            for (int nt = 0; nt < 8; nt++) {
                uint32_t bf[2];
                ldsm_x2(bf, sbK + kboff + (uint32_t)(nt * (8 * KST * 4)) + ks * 32);
                mma_tf32(s[nt][0], s[nt][1], s[nt][2], s[nt][3],
                         qf[ks][0], qf[ks][1], qf[ks][2], qf[ks][3],
                         bf[0], bf[1]);
            }
        }

        // ---- mask (skipped on fully-visible interior tiles) ----
        const bool interior = (kt < 2 * qt) & (allv != 0);
        if (!interior) {
            #pragma unroll
            for (int nt = 0; nt < 8; nt++) {
                const int lc0 = nt * 8 + 2 * tig;
                const int c0g = kv0 + lc0;
                const bool v0 = (msk[lc0] != 0);
                const bool v1 = (msk[lc0 + 1] != 0);
                if (!v0 | (c0g     > q_row0)) s[nt][0] = -1e30f;
                if (!v1 | (c0g + 1 > q_row0)) s[nt][1] = -1e30f;
                if (!v0 | (c0g     > q_row1)) s[nt][2] = -1e30f;
                if (!v1 | (c0g + 1 > q_row1)) s[nt][3] = -1e30f;
            }
        }

        // ---- online softmax ----
        float mx0 = -1e30f, mx1 = -1e30f;
        #pragma unroll
        for (int nt = 0; nt < 8; nt++) {
            mx0 = fmaxf(mx0, fmaxf(s[nt][0], s[nt][1]));
            mx1 = fmaxf(mx1, fmaxf(s[nt][2], s[nt][3]));
        }
        mx0 = fmaxf(mx0, __shfl_xor_sync(0xffffffffu, mx0, 1));
        mx0 = fmaxf(mx0, __shfl_xor_sync(0xffffffffu, mx0, 2));
        mx1 = fmaxf(mx1, __shfl_xor_sync(0xffffffffu, mx1, 1));
        mx1 = fmaxf(mx1, __shfl_xor_sync(0xffffffffu, mx1, 2));

        const float mn0 = fmaxf(m0r, mx0);
        const float mn1 = fmaxf(m1r, mx1);
        const float cr0 = exp2f(m0r - mn0);
        const float cr1 = exp2f(m1r - mn1);
        l0 *= cr0;  l1 *= cr1;
        m0r = mn0;  m1r = mn1;
        #pragma unroll
        for (int nt = 0; nt < 8; nt++) {
            o[nt][0] *= cr0; o[nt][1] *= cr0;
            o[nt][2] *= cr1; o[nt][3] *= cr1;
        }

        // ---- p = exp2(s - m); store P slice (tf32) ----
        #pragma unroll
        for (int nt = 0; nt < 8; nt++) {
            const float p0 = exp2f(s[nt][0] - mn0);
            const float p1 = exp2f(s[nt][1] - mn0);
            const float p2 = exp2f(s[nt][2] - mn1);
            const float p3 = exp2f(s[nt][3] - mn1);
            l0 += p0 + p1;
            l1 += p2 + p3;
            const int col = nt * 8 + 2 * tig;
            float* pr0 = &Ps[(mw + grp    ) * KST + col];
            float* pr1 = &Ps[(mw + grp + 8) * KST + col];
            pr0[0] = f2tf32f(p0);
            pr0[1] = f2tf32f(p1);
            pr1[0] = f2tf32f(p2);
            pr1[1] = f2tf32f(p3);
        }
        __syncwarp();

        // ---- O += P @ V ----
        #pragma unroll
        for (int ks = 0; ks < 8; ks++) {
            const int k8 = ks * 8;
            uint32_t a[4];
            ldsm_x4(a, sbP + paoff + ks * 32);
            #pragma unroll
            for (int nt = 0; nt < 8; nt++) {
                const uint32_t b0 = __float_as_uint(Vs[(k8 + tig    ) * VSTR + nt * 8 + grp]);
                const uint32_t b1 = __float_as_uint(Vs[(k8 + tig + 4) * VSTR + nt * 8 + grp]);
                mma_tf32(o[nt][0], o[nt][1], o[nt][2], o[nt][3],
                         a[0], a[1], a[2], a[3], b0, b1);
            }
        }
    }

    // ---- finalize: tf32-round output (out_gemm reads it raw via cp.async) ----
    l0 += __shfl_xor_sync(0xffffffffu, l0, 1);
    l0 += __shfl_xor_sync(0xffffffffu, l0, 2);
    l1 += __shfl_xor_sync(0xffffffffu, l1, 1);
    l1 += __shfl_xor_sync(0xffffffffu, l1, 2);
    const float inv0 = 1.f / l0;
    const float inv1 = 1.f / l1;

    float* o0 = Og + ((size_t)(b * SEQ + q_row0)) * EMB + h * HD;
    float* o1 = Og + ((size_t)(b * SEQ + q_row1)) * EMB + h * HD;
    #pragma unroll
    for (int nt = 0; nt < 8; nt++) {
        const int col = nt * 8 + 2 * tig;
        *(float2*)(o0 + col) = make_float2(f2tf32f(o[nt][0] * inv0), f2tf32f(o[nt][1] * inv0));
        *(float2*)(o1 + col) = make_float2(f2tf32f(o[nt][2] * inv1), f2tf32f(o[nt][3] * inv1));
    }
}

// ---------------- launch --------------------------------------------------------
extern "C" void kernel_launch(void* const* d_in, const int* in_sizes, int n_in,
                              void* d_out, int out_size)
{
    const float* x  = (const float*)d_in[0];
    const int*   am = (const int*)  d_in[1];
    const float* wq = (const float*)d_in[2];
    const float* wk = (const float*)d_in[3];
    const float* wv = (const float*)d_in[4];
    const float* wo = (const float*)d_in[5];
    float* out = (float*)d_out;

    float *pq, *pk, *pv, *pao, *px32, *pwt;
    cudaGetSymbolAddress((void**)&pq,   g_q);
    cudaGetSymbolAddress((void**)&pk,   g_k);
    cudaGetSymbolAddress((void**)&pv,   g_v);
    cudaGetSymbolAddress((void**)&pao,  g_ao);
    cudaGetSymbolAddress((void**)&px32, g_x32);
    cudaGetSymbolAddress((void**)&pwt,  g_wt);

    // unconditional attribute sets (no static guards; host-side, capture-safe)
    cudaFuncSetAttribute(qkv_gemm, cudaFuncAttributeMaxDynamicSharedMemorySize, GSMEM_BYTES);
    cudaFuncSetAttribute(out_gemm, cudaFuncAttributeMaxDynamicSharedMemorySize, GSMEM_BYTES);
    cudaFuncSetAttribute(flash_tc, cudaFuncAttributeMaxDynamicSharedMemorySize, FLASH_SMEM_BYTES);

    cvt_x_kernel<<<2048, 256>>>((const float4*)x, (float4*)px32, MROWS * EMB / 4);
    cvt_w_kernel<<<dim3(256, 1, 4), 256>>>((const float4*)wq, (const float4*)wk,
                                           (const float4*)wv, (const float4*)wo,
                                           (float4*)pwt);

    qkv_gemm<<<dim3(EMB / BN, MROWS / BM, 3), 256, GSMEM_BYTES>>>(px32, pwt, pq, pk, pv);

    flash_tc<<<dim3(BATCH * NH, SEQ / 128), 256, FLASH_SMEM_BYTES>>>(pq, pk, pv, am, pao);

    out_gemm<<<dim3(EMB / BN, MROWS / BM), 256, GSMEM_BYTES>>>(pao, pwt + (size_t)3 * WSZ, out);
}

// round 13
// speedup vs baseline: 1.1535x; 1.1535x over previous
#include <cuda_runtime.h>
#include <stdint.h>

#define EMB   1024
#define NH    16
#define HD    64
#define BATCH 4
#define SEQ   2048
#define MROWS (BATCH*SEQ)   // 8192
#define KDIM  EMB           // 1024

// ---------------- scratch (static __device__, allocation-guard safe) ----------
__device__ float g_q [(size_t)BATCH*NH*SEQ*HD];   // [B,H,S,D]
__device__ float g_k [(size_t)BATCH*NH*SEQ*HD];
__device__ float g_v [(size_t)BATCH*NH*SEQ*HD];
__device__ float g_ao[(size_t)MROWS*EMB];         // attention out, [B,S,E]

// ---------------- TF32 / MMA / LDSM helpers ------------------------------------
__device__ __forceinline__ uint32_t f2tf32(float x) {
    uint32_t r;
    asm("cvt.rna.tf32.f32 %0, %1;" : "=r"(r) : "f"(x));
    return r;
}
__device__ __forceinline__ float f2tf32f(float x) {
    return __uint_as_float(f2tf32(x));
}

__device__ __forceinline__ void mma_tf32(float& d0, float& d1, float& d2, float& d3,
                                         uint32_t a0, uint32_t a1, uint32_t a2, uint32_t a3,
                                         uint32_t b0, uint32_t b1)
{
    asm volatile(
        "mma.sync.aligned.m16n8k8.row.col.f32.tf32.tf32.f32 "
        "{%0,%1,%2,%3}, {%4,%5,%6,%7}, {%8,%9}, {%0,%1,%2,%3};"
        : "+f"(d0), "+f"(d1), "+f"(d2), "+f"(d3)
        : "r"(a0), "r"(a1), "r"(a2), "r"(a3), "r"(b0), "r"(b1));
}

// ldmatrix on 32-bit (tf32) data viewed as b16 pairs.
__device__ __forceinline__ void ldsm_x4(uint32_t* r, uint32_t addr) {
    asm volatile("ldmatrix.sync.aligned.m8n8.x4.shared.b16 {%0,%1,%2,%3}, [%4];"
                 : "=r"(r[0]), "=r"(r[1]), "=r"(r[2]), "=r"(r[3]) : "r"(addr));
}
__device__ __forceinline__ void ldsm_x2(uint32_t* r, uint32_t addr) {
    asm volatile("ldmatrix.sync.aligned.m8n8.x2.shared.b16 {%0,%1}, [%2];"
                 : "=r"(r[0]), "=r"(r[1]) : "r"(addr));
}

// ---------------- TF32 tensor-core GEMM (double-buffered, ldmatrix) ------------
// C[M,N] = A[M,K] @ W[N,K]^T.  Block 128x128x32, 8 warps (2x4), warp tile 64x32.
// Row-major smem tiles (stride 36): STS.128 staging conflict-free,
// ldmatrix rows land (4*row+col)%32 -> conflict-free fragment loads.
#define BM 128
#define BN 128
#define BK 32
#define GST 36
#define BUF_FLOATS (2*BM*GST)            // As + Ws = 9216 floats per buffer
#define GSMEM_BYTES (2*BUF_FLOATS*4)     // 73728

template<bool SPLIT>
__device__ __forceinline__ void gemm_body(const float* __restrict__ A,
                                          const float* __restrict__ W,
                                          float* __restrict__ C,
                                          float* __restrict__ sm)
{
    const int tid    = threadIdx.x;
    const int lane   = tid & 31;
    const int warp   = tid >> 5;
    const int warp_m = warp >> 2;           // 0..1
    const int warp_n = warp & 3;            // 0..3
    const int m0     = blockIdx.y * BM;
    const int n0     = blockIdx.x * BN;
    const int mw     = warp_m * 64;
    const int nw     = warp_n * 32;

    const uint32_t sbase = (uint32_t)__cvta_generic_to_shared(sm);

    // per-lane ldmatrix byte offsets within a buffer
    uint32_t aoff[4], boff2[2];
    #pragma unroll
    for (int mi = 0; mi < 4; mi++)
        aoff[mi] = (uint32_t)(((mw + mi * 16 + (lane & 15)) * GST + 4 * (lane >> 4)) * 4);
    // paired B-fragments: x4 covers ni = {2j, 2j+1}
    //   lanes 0-7:  ni=2j rows, k 0-3 | lanes 8-15:  ni=2j rows, k 4-7
    //   lanes16-23: ni=2j+1 rows, k 0-3 | lanes 24-31: ni=2j+1 rows, k 4-7
    #pragma unroll
    for (int j = 0; j < 2; j++)
        boff2[j] = (uint32_t)(((nw + (2 * j + (lane >> 4)) * 8 + (lane & 7)) * GST
                               + 4 * ((lane >> 3) & 1) + BM * GST) * 4);

    const int srow = tid >> 3;              // 0..31 (+32p)
    const int scol = (tid & 7) * 4;         // 0,4,..,28

    float acc[4][4][4];
    #pragma unroll
    for (int i = 0; i < 4; i++)
        #pragma unroll
        for (int j = 0; j < 4; j++)
            #pragma unroll
            for (int c = 0; c < 4; c++) acc[i][j][c] = 0.f;

    float4 sa[4], sw[4];
    // slab 0 -> regs
    #pragma unroll
    for (int p = 0; p < 4; p++) {
        const int row = srow + p * 32;
        sa[p] = *(const float4*)(A + (size_t)(m0 + row) * KDIM + scol);
        sw[p] = *(const float4*)(W + (size_t)(n0 + row) * KDIM + scol);
    }
    // stage slab 0 -> buf0
    #pragma unroll
    for (int p = 0; p < 4; p++) {
        const int row = srow + p * 32;
        float* ap = sm + row * GST + scol;
        ap[0] = f2tf32f(sa[p].x); ap[1] = f2tf32f(sa[p].y);
        ap[2] = f2tf32f(sa[p].z); ap[3] = f2tf32f(sa[p].w);
        float* wp = sm + BM * GST + row * GST + scol;
        wp[0] = f2tf32f(sw[p].x); wp[1] = f2tf32f(sw[p].y);
        wp[2] = f2tf32f(sw[p].z); wp[3] = f2tf32f(sw[p].w);
    }
    // slab 1 -> regs
    #pragma unroll
    for (int p = 0; p < 4; p++) {
        const int row = srow + p * 32;
        sa[p] = *(const float4*)(A + (size_t)(m0 + row) * KDIM + BK + scol);
        sw[p] = *(const float4*)(W + (size_t)(n0 + row) * KDIM + BK + scol);
    }
    __syncthreads();

    const int NIT = KDIM / BK;   // 32
    for (int it = 0; it < NIT; it++) {
        // stage regs (slab it+1) into the idle buffer; overlaps compute below
        if (it < NIT - 1) {
            float* dst = sm + ((it + 1) & 1) * BUF_FLOATS;
            #pragma unroll
            for (int p = 0; p < 4; p++) {
                const int row = srow + p * 32;
                float* ap = dst + row * GST + scol;
                ap[0] = f2tf32f(sa[p].x); ap[1] = f2tf32f(sa[p].y);
                ap[2] = f2tf32f(sa[p].z); ap[3] = f2tf32f(sa[p].w);
                float* wp = dst + BM * GST + row * GST + scol;
                wp[0] = f2tf32f(sw[p].x); wp[1] = f2tf32f(sw[p].y);
                wp[2] = f2tf32f(sw[p].z); wp[3] = f2tf32f(sw[p].w);
            }
        }
        // prefetch slab it+2
        if (it < NIT - 2) {
            const int kk = (it + 2) * BK + scol;
            #pragma unroll
            for (int p = 0; p < 4; p++) {
                const int row = srow + p * 32;
                sa[p] = *(const float4*)(A + (size_t)(m0 + row) * KDIM + kk);
                sw[p] = *(const float4*)(W + (size_t)(n0 + row) * KDIM + kk);
            }
        }
        // compute from current buffer
        const uint32_t bufo = (uint32_t)((it & 1) * BUF_FLOATS * 4);
        #pragma unroll
        for (int kb = 0; kb < 4; kb++) {
            const uint32_t ko = bufo + kb * 32;   // 8 floats = 32 bytes per k-block
            uint32_t af[4][4];
            #pragma unroll
            for (int mi = 0; mi < 4; mi++)
                ldsm_x4(af[mi], sbase + ko + aoff[mi]);
            uint32_t bf[2][4];                    // [pair][regs: ni-even b0,b1, ni-odd b0,b1]
            #pragma unroll
            for (int j = 0; j < 2; j++)
                ldsm_x4(bf[j], sbase + ko + boff2[j]);
            #pragma unroll
            for (int mi = 0; mi < 4; mi++)
                #pragma unroll
                for (int ni = 0; ni < 4; ni++)
                    mma_tf32(acc[mi][ni][0], acc[mi][ni][1], acc[mi][ni][2], acc[mi][ni][3],
                             af[mi][0], af[mi][1], af[mi][2], af[mi][3],
                             bf[ni >> 1][(ni & 1) * 2], bf[ni >> 1][(ni & 1) * 2 + 1]);
        }
        __syncthreads();
    }

    // ---- epilogue ----
    const int grp = lane >> 2;
    const int tig = lane & 3;
    #pragma unroll
    for (int mi = 0; mi < 4; mi++) {
        #pragma unroll
        for (int ni = 0; ni < 4; ni++) {
            const int row = m0 + mw + mi * 16 + grp;
            const int col = n0 + nw + ni * 8 + 2 * tig;
            #pragma unroll
            for (int half = 0; half < 2; half++) {
                const int m = row + half * 8;
                const float v0 = acc[mi][ni][half * 2 + 0];
                const float v1 = acc[mi][ni][half * 2 + 1];
                size_t idx;
                if (SPLIT) {   // [B,H,S,D]
                    const int b = m >> 11, s = m & 2047, h = col >> 6, d = col & 63;
                    idx = ((size_t)(b * NH + h) * SEQ + s) * HD + d;
                } else {
                    idx = (size_t)m * EMB + col;
                }
                *(float2*)(C + idx) = make_float2(v0, v1);
            }
        }
    }
}

// fused QKV: gridDim.z = 3 selects weight/output
__global__ void __launch_bounds__(256)
qkv_gemm(const float* __restrict__ x,
         const float* __restrict__ wq, const float* __restrict__ wk,
         const float* __restrict__ wv,
         float* __restrict__ pq, float* __restrict__ pk, float* __restrict__ pv)
{
    extern __shared__ __align__(16) float smg[];
    const int z = blockIdx.z;
    const float* W = (z == 0) ? wq : (z == 1) ? wk : wv;
    float*       C = (z == 0) ? pq : (z == 1) ? pk : pv;
    gemm_body<true>(x, W, C, smg);
}

__global__ void __launch_bounds__(256)
out_gemm(const float* __restrict__ A, const float* __restrict__ W,
         float* __restrict__ C)
{
    extern __shared__ __align__(16) float smg[];
    gemm_body<false>(A, W, C, smg);
}

// ---------------- tensor-core causal flash attention ---------------------------
// CTA: 128 q-rows of one (b,h). 8 warps x 16 q-rows. KV tiles of 64.
// Row-major smem (K/P stride 68, V stride 72); Q/K/P fragments via ldmatrix.
#define KST 68
#define VSTR 72
#define FLASH_SMEM_FLOATS (64*KST + 64*VSTR + 128*KST)
#define FLASH_SMEM_BYTES  (FLASH_SMEM_FLOATS*4 + 64*4)

__global__ void __launch_bounds__(256, 2)
flash_tc(const float* __restrict__ Qg, const float* __restrict__ Kg,
         const float* __restrict__ Vg, const int* __restrict__ maskg,
         float* __restrict__ Og)
{
    extern __shared__ __align__(16) float sm[];
    float* Ks = sm;                    // [64][KST]
    float* Vs = Ks + 64 * KST;         // [64][VSTR]
    float* Ps = Vs + 64 * VSTR;        // [128][KST]  (Q staging, then P)
    int*   msk = (int*)(Ps + 128 * KST);

    const int bh   = blockIdx.x;
    const int b    = bh >> 4;
    const int h    = bh & 15;
    const int qt   = gridDim.y - 1 - blockIdx.y;   // heavy tiles first
    const int q0   = qt * 128;
    const int tid  = threadIdx.x;
    const int lane = tid & 31;
    const int warp = tid >> 5;
    const int grp  = lane >> 2;
    const int tig  = lane & 3;
    const int mw   = warp * 16;

    const uint32_t sbK = (uint32_t)__cvta_generic_to_shared(Ks);
    const uint32_t sbP = (uint32_t)__cvta_generic_to_shared(Ps);
    // ldmatrix per-lane offsets
    const uint32_t paoff = (uint32_t)(((mw + (lane & 15)) * KST + 4 * (lane >> 4)) * 4);
    // paired K-fragments: x4 covers nt = {2j, 2j+1}
    uint32_t kboff2[4];
    #pragma unroll
    for (int j = 0; j < 4; j++)
        kboff2[j] = (uint32_t)((((2 * j + (lane >> 4)) * 8 + (lane & 7)) * KST
                                + 4 * ((lane >> 3) & 1)) * 4);

    const float qscale = 0.125f * 1.44269504088896f;  // 1/sqrt(64) * log2(e)

    // ---- stage Q tile [128 x 64] (scaled, tf32) into Ps ----
    #pragma unroll
    for (int p = 0; p < 8; p++) {
        const int idx = tid + p * 256;
        const int row = idx >> 4;
        const int col = (idx & 15) * 4;
        float4 t = *(const float4*)(Qg + ((size_t)bh * SEQ + q0 + row) * HD + col);
        float* dp = &Ps[row * KST + col];
        dp[0] = f2tf32f(t.x * qscale);
        dp[1] = f2tf32f(t.y * qscale);
        dp[2] = f2tf32f(t.z * qscale);
        dp[3] = f2tf32f(t.w * qscale);
    }
    __syncthreads();

    uint32_t qf[8][4];
    #pragma unroll
    for (int ks = 0; ks < 8; ks++)
        ldsm_x4(qf[ks], sbP + paoff + ks * 32);

    float o[8][4];
    #pragma unroll
    for (int nt = 0; nt < 8; nt++)
        #pragma unroll
        for (int c = 0; c < 4; c++) o[nt][c] = 0.f;
    float m0r = -1e30f, m1r = -1e30f, l0 = 0.f, l1 = 0.f;

    const int q_row0 = q0 + mw + grp;
    const int q_row1 = q_row0 + 8;
    const int* mrow  = maskg + b * SEQ;
    const int  ntile = 2 * qt + 2;

    for (int kt = 0; kt < ntile; kt++) {
        const int kv0 = kt * 64;
        __syncthreads();   // previous tile's Ks/Vs (and P) reads complete

        // ---- load K,V tiles (tf32) + mask ----
        #pragma unroll
        for (int p = 0; p < 4; p++) {
            const int idx = tid + p * 256;
            const int row = idx >> 4;
            const int col = (idx & 15) * 4;
            float4 tk = *(const float4*)(Kg + ((size_t)bh * SEQ + kv0 + row) * HD + col);
            float* kp = &Ks[row * KST + col];
            kp[0] = f2tf32f(tk.x); kp[1] = f2tf32f(tk.y);
            kp[2] = f2tf32f(tk.z); kp[3] = f2tf32f(tk.w);
            float4 tv = *(const float4*)(Vg + ((size_t)bh * SEQ + kv0 + row) * HD + col);
            float* vp = &Vs[row * VSTR + col];
            vp[0] = f2tf32f(tv.x); vp[1] = f2tf32f(tv.y);
            vp[2] = f2tf32f(tv.z); vp[3] = f2tf32f(tv.w);
        }
        int mv = 1;
        if (tid < 64) { mv = mrow[kv0 + tid]; msk[tid] = mv; }
        const int allv = __syncthreads_and(mv != 0);   // barrier + all-reduce

        // ---- S = Q @ K^T ----
        float s[8][4];
        #pragma unroll
        for (int nt = 0; nt < 8; nt++)
            #pragma unroll
            for (int c = 0; c < 4; c++) s[nt][c] = 0.f;

        #pragma unroll
        for (int ks = 0; ks < 8; ks++) {
            uint32_t kf[4][4];
            #pragma unroll
            for (int j = 0; j < 4; j++)
                ldsm_x4(kf[j], sbK + kboff2[j] + ks * 32);
            #pragma unroll
            for (int nt = 0; nt < 8; nt++)
                mma_tf32(s[nt][0], s[nt][1], s[nt][2], s[nt][3],
                         qf[ks][0], qf[ks][1], qf[ks][2], qf[ks][3],
                         kf[nt >> 1][(nt & 1) * 2], kf[nt >> 1][(nt & 1) * 2 + 1]);
        }

        // ---- mask (skipped on fully-visible interior tiles) ----
        const bool interior = (kt < 2 * qt) & (allv != 0);
        if (!interior) {
            #pragma unroll
            for (int nt = 0; nt < 8; nt++) {
                const int lc0 = nt * 8 + 2 * tig;
                const int c0g = kv0 + lc0;
                const bool v0 = (msk[lc0] != 0);
                const bool v1 = (msk[lc0 + 1] != 0);
                if (!v0 | (c0g     > q_row0)) s[nt][0] = -1e30f;
                if (!v1 | (c0g + 1 > q_row0)) s[nt][1] = -1e30f;
                if (!v0 | (c0g     > q_row1)) s[nt][2] = -1e30f;
                if (!v1 | (c0g + 1 > q_row1)) s[nt][3] = -1e30f;
            }
        }

        // ---- online softmax ----
        float mx0 = -1e30f, mx1 = -1e30f;
        #pragma unroll
        for (int nt = 0; nt < 8; nt++) {
            mx0 = fmaxf(mx0, fmaxf(s[nt][0], s[nt][1]));
            mx1 = fmaxf(mx1, fmaxf(s[nt][2], s[nt][3]));
        }
        mx0 = fmaxf(mx0, __shfl_xor_sync(0xffffffffu, mx0, 1));
        mx0 = fmaxf(mx0, __shfl_xor_sync(0xffffffffu, mx0, 2));
        mx1 = fmaxf(mx1, __shfl_xor_sync(0xffffffffu, mx1, 1));
        mx1 = fmaxf(mx1, __shfl_xor_sync(0xffffffffu, mx1, 2));

        const float mn0 = fmaxf(m0r, mx0);
        const float mn1 = fmaxf(m1r, mx1);
        const float cr0 = exp2f(m0r - mn0);
        const float cr1 = exp2f(m1r - mn1);
        l0 *= cr0;  l1 *= cr1;
        m0r = mn0;  m1r = mn1;
        #pragma unroll
        for (int nt = 0; nt < 8; nt++) {
            o[nt][0] *= cr0; o[nt][1] *= cr0;
            o[nt][2] *= cr1; o[nt][3] *= cr1;
        }

        // ---- p = exp2(s - m); store P slice (tf32) ----
        #pragma unroll
        for (int nt = 0; nt < 8; nt++) {
            const float p0 = exp2f(s[nt][0] - mn0);
            const float p1 = exp2f(s[nt][1] - mn0);
            const float p2 = exp2f(s[nt][2] - mn1);
            const float p3 = exp2f(s[nt][3] - mn1);
            l0 += p0 + p1;
            l1 += p2 + p3;
            const int col = nt * 8 + 2 * tig;
            float* pr0 = &Ps[(mw + grp    ) * KST + col];
            float* pr1 = &Ps[(mw + grp + 8) * KST + col];
            pr0[0] = f2tf32f(p0);
            pr0[1] = f2tf32f(p1);
            pr1[0] = f2tf32f(p2);
            pr1[1] = f2tf32f(p3);
        }
        __syncwarp();

        // ---- O += P @ V ----
        #pragma unroll
        for (int ks = 0; ks < 8; ks++) {
            const int k8 = ks * 8;
            uint32_t a[4];
            ldsm_x4(a, sbP + paoff + ks * 32);
            #pragma unroll
            for (int nt = 0; nt < 8; nt++) {
                const uint32_t b0 = __float_as_uint(Vs[(k8 + tig    ) * VSTR + nt * 8 + grp]);
                const uint32_t b1 = __float_as_uint(Vs[(k8 + tig + 4) * VSTR + nt * 8 + grp]);
                mma_tf32(o[nt][0], o[nt][1], o[nt][2], o[nt][3],
                         a[0], a[1], a[2], a[3], b0, b1);
            }
        }
    }

    // ---- finalize ----
    l0 += __shfl_xor_sync(0xffffffffu, l0, 1);
    l0 += __shfl_xor_sync(0xffffffffu, l0, 2);
    l1 += __shfl_xor_sync(0xffffffffu, l1, 1);
    l1 += __shfl_xor_sync(0xffffffffu, l1, 2);
    const float inv0 = 1.f / l0;
    const float inv1 = 1.f / l1;

    float* o0 = Og + ((size_t)(b * SEQ + q_row0)) * EMB + h * HD;
    float* o1 = Og + ((size_t)(b * SEQ + q_row1)) * EMB + h * HD;
    #pragma unroll
    for (int nt = 0; nt < 8; nt++) {
        const int col = nt * 8 + 2 * tig;
        *(float2*)(o0 + col) = make_float2(o[nt][0] * inv0, o[nt][1] * inv0);
        *(float2*)(o1 + col) = make_float2(o[nt][2] * inv1, o[nt][3] * inv1);
    }
}

// ---------------- launch --------------------------------------------------------
extern "C" void kernel_launch(void* const* d_in, const int* in_sizes, int n_in,
                              void* d_out, int out_size)
{
    const float* x  = (const float*)d_in[0];
    const int*   am = (const int*)  d_in[1];
    const float* wq = (const float*)d_in[2];
    const float* wk = (const float*)d_in[3];
    const float* wv = (const float*)d_in[4];
    const float* wo = (const float*)d_in[5];
    float* out = (float*)d_out;

    float *pq, *pk, *pv, *pao;
    cudaGetSymbolAddress((void**)&pq,  g_q);
    cudaGetSymbolAddress((void**)&pk,  g_k);
    cudaGetSymbolAddress((void**)&pv,  g_v);
    cudaGetSymbolAddress((void**)&pao, g_ao);

    // unconditional attribute sets (no static guards; host-side, capture-safe)
    cudaFuncSetAttribute(qkv_gemm, cudaFuncAttributeMaxDynamicSharedMemorySize, GSMEM_BYTES);
    cudaFuncSetAttribute(out_gemm, cudaFuncAttributeMaxDynamicSharedMemorySize, GSMEM_BYTES);
    cudaFuncSetAttribute(flash_tc, cudaFuncAttributeMaxDynamicSharedMemorySize, FLASH_SMEM_BYTES);

    qkv_gemm<<<dim3(EMB / BN, MROWS / BM, 3), 256, GSMEM_BYTES>>>(x, wq, wk, wv, pq, pk, pv);

    flash_tc<<<dim3(BATCH * NH, SEQ / 128), 256, FLASH_SMEM_BYTES>>>(pq, pk, pv, am, pao);

    out_gemm<<<dim3(EMB / BN, MROWS / BM), 256, GSMEM_BYTES>>>(pao, wo, out);
}

// round 16
// speedup vs baseline: 1.8297x; 1.5862x over previous
#include <cuda_runtime.h>
#include <cuda_fp16.h>
#include <stdint.h>

#define EMB   1024
#define NH    16
#define HD    64
#define BATCH 4
#define SEQ   2048
#define MROWS (BATCH*SEQ)   // 8192
#define KDIM  EMB           // 1024
#define WSZ   (EMB*EMB)

// ---------------- scratch (static __device__, allocation-guard safe) ----------
__device__ __align__(16) __half g_xh[(size_t)MROWS*EMB];        // fp16 x
__device__ __align__(16) __half g_wh[(size_t)4*WSZ];            // fp16 wq,wk,wv,wo
__device__ __align__(16) __half g_q [(size_t)BATCH*NH*SEQ*HD];  // [B,H,S,D] (q pre-scaled)
__device__ __align__(16) __half g_k [(size_t)BATCH*NH*SEQ*HD];
__device__ __align__(16) __half g_v [(size_t)BATCH*NH*SEQ*HD];
__device__ __align__(16) __half g_ao[(size_t)MROWS*EMB];        // attention out [B,S,E]

// ---------------- MMA / LDSM helpers -------------------------------------------
__device__ __forceinline__ void mma_f16(float& d0, float& d1, float& d2, float& d3,
                                        uint32_t a0, uint32_t a1, uint32_t a2, uint32_t a3,
                                        uint32_t b0, uint32_t b1)
{
    asm volatile(
        "mma.sync.aligned.m16n8k16.row.col.f32.f16.f16.f32 "
        "{%0,%1,%2,%3}, {%4,%5,%6,%7}, {%8,%9}, {%0,%1,%2,%3};"
        : "+f"(d0), "+f"(d1), "+f"(d2), "+f"(d3)
        : "r"(a0), "r"(a1), "r"(a2), "r"(a3), "r"(b0), "r"(b1));
}

__device__ __forceinline__ void ldsm_x4(uint32_t* r, uint32_t addr) {
    asm volatile("ldmatrix.sync.aligned.m8n8.x4.shared.b16 {%0,%1,%2,%3}, [%4];"
                 : "=r"(r[0]), "=r"(r[1]), "=r"(r[2]), "=r"(r[3]) : "r"(addr));
}
__device__ __forceinline__ void ldsm_x4t(uint32_t* r, uint32_t addr) {
    asm volatile("ldmatrix.sync.aligned.m8n8.x4.trans.shared.b16 {%0,%1,%2,%3}, [%4];"
                 : "=r"(r[0]), "=r"(r[1]), "=r"(r[2]), "=r"(r[3]) : "r"(addr));
}

__device__ __forceinline__ uint32_t h2u(__half2 h) {
    uint32_t u; *(__half2*)&u = h; return u;
}

// ---------------- fp32 -> fp16 convert kernels (memory-bound, ~10us) -----------
__global__ void cvt_x_kernel(const float4* __restrict__ src, uint2* __restrict__ dst,
                             int n4)
{
    for (int i = blockIdx.x * blockDim.x + threadIdx.x; i < n4;
         i += gridDim.x * blockDim.x) {
        float4 t = src[i];
        uint2 u;
        u.x = h2u(__floats2half2_rn(t.x, t.y));
        u.y = h2u(__floats2half2_rn(t.z, t.w));
        dst[i] = u;
    }
}

__global__ void cvt_w_kernel(const float4* __restrict__ wq, const float4* __restrict__ wk,
                             const float4* __restrict__ wv, const float4* __restrict__ wo,
                             uint2* __restrict__ dst)
{
    const int z = blockIdx.z;
    const float4* src = (z == 0) ? wq : (z == 1) ? wk : (z == 2) ? wv : wo;
    uint2* d = dst + (size_t)z * (WSZ / 4);
    for (int i = blockIdx.x * blockDim.x + threadIdx.x; i < WSZ / 4;
         i += gridDim.x * blockDim.x) {
        float4 t = src[i];
        uint2 u;
        u.x = h2u(__floats2half2_rn(t.x, t.y));
        u.y = h2u(__floats2half2_rn(t.z, t.w));
        d[i] = u;
    }
}

// ---------------- FP16 tensor-core GEMM (double-buffered, ldmatrix) ------------
// C[M,N] = A[M,K] @ W[N,K]^T.  Block 128x128x32, 8 warps (2x4), warp tile 64x32.
// Row-major half tiles, stride 40 halves: ldmatrix rows land 20*r%32 -> distinct.
#define BM 128
#define BN 128
#define BKH 32                     // K halves per slab
#define RS 40                      // halves per row
#define ATILE_H (BM*RS)            // 5120 halves
#define BUF_H (2*ATILE_H)          // A + W per buffer
#define GSMEM_BYTES (2*BUF_H*2)    // 40960 bytes

#define QSCALE (0.125f * 1.44269504088896f)   // 1/sqrt(64) * log2(e)

template<bool SPLIT>
__device__ __forceinline__ void gemm_h(const __half* __restrict__ A,
                                       const __half* __restrict__ W,
                                       void* __restrict__ Cv,
                                       __half* __restrict__ sm, float esc)
{
    const int tid    = threadIdx.x;
    const int lane   = tid & 31;
    const int warp   = tid >> 5;
    const int warp_m = warp >> 2;           // 0..1
    const int warp_n = warp & 3;            // 0..3
    const int m0     = blockIdx.y * BM;
    const int n0     = blockIdx.x * BN;
    const int mw     = warp_m * 64;
    const int nw     = warp_n * 32;

    const uint32_t sbase = (uint32_t)__cvta_generic_to_shared(sm);

    uint32_t aoff[4], boff2[2];
    #pragma unroll
    for (int mi = 0; mi < 4; mi++)
        aoff[mi] = (uint32_t)(((mw + mi * 16 + (lane & 15)) * RS + (lane >> 4) * 8) * 2);
    #pragma unroll
    for (int j = 0; j < 2; j++)
        boff2[j] = (uint32_t)(((nw + (2 * j + (lane >> 4)) * 8 + (lane & 7)) * RS
                               + ((lane >> 3) & 1) * 8 + ATILE_H) * 2);

    const int srow = tid >> 2;              // 0..63 (+64p)
    const int sseg = (tid & 3) * 8;         // halves 0,8,16,24

    float acc[4][4][4];
    #pragma unroll
    for (int i = 0; i < 4; i++)
        #pragma unroll
        for (int j = 0; j < 4; j++)
            #pragma unroll
            for (int c = 0; c < 4; c++) acc[i][j][c] = 0.f;

    uint4 sa[2], sw[2];
    // slab 0 -> regs -> buf0
    #pragma unroll
    for (int p = 0; p < 2; p++) {
        const int row = srow + p * 64;
        sa[p] = *(const uint4*)(A + (size_t)(m0 + row) * KDIM + sseg);
        sw[p] = *(const uint4*)(W + (size_t)(n0 + row) * KDIM + sseg);
    }
    #pragma unroll
    for (int p = 0; p < 2; p++) {
        const int row = srow + p * 64;
        *(uint4*)(sm + row * RS + sseg)            = sa[p];
        *(uint4*)(sm + ATILE_H + row * RS + sseg)  = sw[p];
    }
    // slab 1 -> regs
    #pragma unroll
    for (int p = 0; p < 2; p++) {
        const int row = srow + p * 64;
        sa[p] = *(const uint4*)(A + (size_t)(m0 + row) * KDIM + BKH + sseg);
        sw[p] = *(const uint4*)(W + (size_t)(n0 + row) * KDIM + BKH + sseg);
    }
    __syncthreads();

    const int NIT = KDIM / BKH;   // 32
    for (int it = 0; it < NIT; it++) {
        if (it < NIT - 1) {
            __half* dst = sm + ((it + 1) & 1) * BUF_H;
            #pragma unroll
            for (int p = 0; p < 2; p++) {
                const int row = srow + p * 64;
                *(uint4*)(dst + row * RS + sseg)           = sa[p];
                *(uint4*)(dst + ATILE_H + row * RS + sseg) = sw[p];
            }
        }
        if (it < NIT - 2) {
            const int kk = (it + 2) * BKH + sseg;
            #pragma unroll
            for (int p = 0; p < 2; p++) {
                const int row = srow + p * 64;
                sa[p] = *(const uint4*)(A + (size_t)(m0 + row) * KDIM + kk);
                sw[p] = *(const uint4*)(W + (size_t)(n0 + row) * KDIM + kk);
            }
        }
        const uint32_t bufo = (uint32_t)((it & 1) * BUF_H * 2);
        #pragma unroll
        for (int ks = 0; ks < 2; ks++) {           // k16 steps
            const uint32_t ko = bufo + ks * 32;    // 16 halves = 32B
            uint32_t af[4][4];
            #pragma unroll
            for (int mi = 0; mi < 4; mi++)
                ldsm_x4(af[mi], sbase + ko + aoff[mi]);
            uint32_t bf[2][4];
            #pragma unroll
            for (int j = 0; j < 2; j++)
                ldsm_x4(bf[j], sbase + ko + boff2[j]);
            #pragma unroll
            for (int mi = 0; mi < 4; mi++)
                #pragma unroll
                for (int ni = 0; ni < 4; ni++)
                    mma_f16(acc[mi][ni][0], acc[mi][ni][1], acc[mi][ni][2], acc[mi][ni][3],
                            af[mi][0], af[mi][1], af[mi][2], af[mi][3],
                            bf[ni >> 1][(ni & 1) * 2], bf[ni >> 1][(ni & 1) * 2 + 1]);
        }
        __syncthreads();
    }

    // ---- epilogue ----
    const int grp = lane >> 2;
    const int tig = lane & 3;
    #pragma unroll
    for (int mi = 0; mi < 4; mi++) {
        #pragma unroll
        for (int ni = 0; ni < 4; ni++) {
            const int row = m0 + mw + mi * 16 + grp;
            const int col = n0 + nw + ni * 8 + 2 * tig;
            #pragma unroll
            for (int half_ = 0; half_ < 2; half_++) {
                const int m = row + half_ * 8;
                const float v0 = acc[mi][ni][half_ * 2 + 0];
                const float v1 = acc[mi][ni][half_ * 2 + 1];
                if (SPLIT) {   // half output, [B,H,S,D]
                    const int b = m >> 11, s = m & 2047, h = col >> 6, d = col & 63;
                    const size_t idx = ((size_t)(b * NH + h) * SEQ + s) * HD + d;
                    *(__half2*)((__half*)Cv + idx) = __floats2half2_rn(v0 * esc, v1 * esc);
                } else {       // fp32 output, [M,EMB]
                    *(float2*)((float*)Cv + (size_t)m * EMB + col) = make_float2(v0, v1);
                }
            }
        }
    }
}

__global__ void __launch_bounds__(256)
qkv_gemm(const __half* __restrict__ xh, const __half* __restrict__ wh,
         __half* __restrict__ pq, __half* __restrict__ pk, __half* __restrict__ pv)
{
    extern __shared__ __align__(16) __half smh[];
    const int z = blockIdx.z;
    const __half* W = wh + (size_t)z * WSZ;
    __half*       C = (z == 0) ? pq : (z == 1) ? pk : pv;
    gemm_h<true>(xh, W, C, smh, (z == 0) ? QSCALE : 1.0f);
}

__global__ void __launch_bounds__(256)
out_gemm(const __half* __restrict__ A, const __half* __restrict__ W,
         float* __restrict__ C)
{
    extern __shared__ __align__(16) __half smh[];
    gemm_h<false>(A, W, C, smh, 1.0f);
}

// ---------------- fp16 tensor-core causal flash attention ----------------------
// CTA: 128 q-rows of one (b,h). 8 warps x 16 q-rows. KV tiles of 64.
// All operands fp16 in smem (stride 72 halves); fp32 accumulators.
#define KSH 72
#define FLASH_SMEM_BYTES ((64*KSH + 64*KSH + 128*KSH)*2 + 64*4)   // 37120

__global__ void __launch_bounds__(256, 2)
flash_tc(const __half* __restrict__ Qg, const __half* __restrict__ Kg,
         const __half* __restrict__ Vg, const int* __restrict__ maskg,
         __half* __restrict__ Og)
{
    extern __shared__ __align__(16) __half smf[];
    __half* Ks = smf;                    // [64][KSH]
    __half* Vs = Ks + 64 * KSH;          // [64][KSH]
    __half* Ps = Vs + 64 * KSH;          // [128][KSH]  (Q staging, then P)
    int*    msk = (int*)(Ps + 128 * KSH);

    const int bh   = blockIdx.x;
    const int b    = bh >> 4;
    const int h    = bh & 15;
    const int qt   = gridDim.y - 1 - blockIdx.y;   // heavy tiles first
    const int q0   = qt * 128;
    const int tid  = threadIdx.x;
    const int lane = tid & 31;
    const int warp = tid >> 5;
    const int grp  = lane >> 2;
    const int tig  = lane & 3;
    const int mw   = warp * 16;

    const uint32_t sbK = (uint32_t)__cvta_generic_to_shared(Ks);
    const uint32_t sbV = (uint32_t)__cvta_generic_to_shared(Vs);
    const uint32_t sbP = (uint32_t)__cvta_generic_to_shared(Ps);

    const uint32_t paoff = (uint32_t)(((mw + (lane & 15)) * KSH + (lane >> 4) * 8) * 2);
    uint32_t kboff2[4], vboff2[4];
    #pragma unroll
    for (int j = 0; j < 4; j++) {
        kboff2[j] = (uint32_t)((((2 * j + (lane >> 4)) * 8 + (lane & 7)) * KSH
                                + ((lane >> 3) & 1) * 8) * 2);
        vboff2[j] = (uint32_t)(((((lane >> 3) & 1) * 8 + (lane & 7)) * KSH
                                + (2 * j + (lane >> 4)) * 8) * 2);
    }

    // ---- stage Q tile [128 x 64] halves (already scaled) ----
    #pragma unroll
    for (int p = 0; p < 4; p++) {
        const int idx = tid + p * 256;
        const int row = idx >> 3;
        const int seg = (idx & 7) * 8;
        *(uint4*)(Ps + row * KSH + seg) =
            *(const uint4*)(Qg + ((size_t)bh * SEQ + q0 + row) * HD + seg);
    }
    __syncthreads();

    uint32_t qf[4][4];
    #pragma unroll
    for (int ks = 0; ks < 4; ks++)
        ldsm_x4(qf[ks], sbP + paoff + ks * 32);

    float o[8][4];
    #pragma unroll
    for (int nt = 0; nt < 8; nt++)
        #pragma unroll
        for (int c = 0; c < 4; c++) o[nt][c] = 0.f;
    float m0r = -1e30f, m1r = -1e30f, l0 = 0.f, l1 = 0.f;

    const int q_row0 = q0 + mw + grp;
    const int q_row1 = q_row0 + 8;
    const int* mrow  = maskg + b * SEQ;
    const int  ntile = 2 * qt + 2;

    for (int kt = 0; kt < ntile; kt++) {
        const int kv0 = kt * 64;
        __syncthreads();   // previous tile's Ks/Vs (and P) reads complete

        // ---- stage K,V tiles (pure fp16 copy) + mask ----
        #pragma unroll
        for (int p = 0; p < 2; p++) {
            const int idx = tid + p * 256;
            const int row = idx >> 3;
            const int seg = (idx & 7) * 8;
            *(uint4*)(Ks + row * KSH + seg) =
                *(const uint4*)(Kg + ((size_t)bh * SEQ + kv0 + row) * HD + seg);
            *(uint4*)(Vs + row * KSH + seg) =
                *(const uint4*)(Vg + ((size_t)bh * SEQ + kv0 + row) * HD + seg);
        }
        int mv = 1;
        if (tid < 64) { mv = mrow[kv0 + tid]; msk[tid] = mv; }
        const int allv = __syncthreads_and(mv != 0);   // barrier + all-reduce

        // ---- S = Q @ K^T ----
        float s[8][4];
        #pragma unroll
        for (int nt = 0; nt < 8; nt++)
            #pragma unroll
            for (int c = 0; c < 4; c++) s[nt][c] = 0.f;

        #pragma unroll
        for (int ks = 0; ks < 4; ks++) {
            uint32_t kf[4][4];
            #pragma unroll
            for (int j = 0; j < 4; j++)
                ldsm_x4(kf[j], sbK + kboff2[j] + ks * 32);
            #pragma unroll
            for (int nt = 0; nt < 8; nt++)
                mma_f16(s[nt][0], s[nt][1], s[nt][2], s[nt][3],
                        qf[ks][0], qf[ks][1], qf[ks][2], qf[ks][3],
                        kf[nt >> 1][(nt & 1) * 2], kf[nt >> 1][(nt & 1) * 2 + 1]);
        }

        // ---- mask (skipped on fully-visible interior tiles) ----
        const bool interior = (kt < 2 * qt) & (allv != 0);
        if (!interior) {
            #pragma unroll
            for (int nt = 0; nt < 8; nt++) {
                const int lc0 = nt * 8 + 2 * tig;
                const int c0g = kv0 + lc0;
                const bool v0 = (msk[lc0] != 0);
                const bool v1 = (msk[lc0 + 1] != 0);
                if (!v0 | (c0g     > q_row0)) s[nt][0] = -1e30f;
                if (!v1 | (c0g + 1 > q_row0)) s[nt][1] = -1e30f;
                if (!v0 | (c0g     > q_row1)) s[nt][2] = -1e30f;
                if (!v1 | (c0g + 1 > q_row1)) s[nt][3] = -1e30f;
            }
        }

        // ---- online softmax (log2 domain) ----
        float mx0 = -1e30f, mx1 = -1e30f;
        #pragma unroll
        for (int nt = 0; nt < 8; nt++) {
            mx0 = fmaxf(mx0, fmaxf(s[nt][0], s[nt][1]));
            mx1 = fmaxf(mx1, fmaxf(s[nt][2], s[nt][3]));
        }
        mx0 = fmaxf(mx0, __shfl_xor_sync(0xffffffffu, mx0, 1));
        mx0 = fmaxf(mx0, __shfl_xor_sync(0xffffffffu, mx0, 2));
        mx1 = fmaxf(mx1, __shfl_xor_sync(0xffffffffu, mx1, 1));
        mx1 = fmaxf(mx1, __shfl_xor_sync(0xffffffffu, mx1, 2));

        const float mn0 = fmaxf(m0r, mx0);
        const float mn1 = fmaxf(m1r, mx1);
        const float cr0 = exp2f(m0r - mn0);
        const float cr1 = exp2f(m1r - mn1);
        l0 *= cr0;  l1 *= cr1;
        m0r = mn0;  m1r = mn1;
        #pragma unroll
        for (int nt = 0; nt < 8; nt++) {
            o[nt][0] *= cr0; o[nt][1] *= cr0;
            o[nt][2] *= cr1; o[nt][3] *= cr1;
        }

        // ---- p = exp2(s - m); store P (fp16) ----
        #pragma unroll
        for (int nt = 0; nt < 8; nt++) {
            const float p0 = exp2f(s[nt][0] - mn0);
            const float p1 = exp2f(s[nt][1] - mn0);
            const float p2 = exp2f(s[nt][2] - mn1);
            const float p3 = exp2f(s[nt][3] - mn1);
            l0 += p0 + p1;
            l1 += p2 + p3;
            const int col = nt * 8 + 2 * tig;
            *(__half2*)(Ps + (mw + grp    ) * KSH + col) = __floats2half2_rn(p0, p1);
            *(__half2*)(Ps + (mw + grp + 8) * KSH + col) = __floats2half2_rn(p2, p3);
        }
        __syncwarp();

        // ---- O += P @ V  (V via ldmatrix.trans) ----
        #pragma unroll
        for (int ks = 0; ks < 4; ks++) {
            uint32_t a[4];
            ldsm_x4(a, sbP + paoff + ks * 32);
            uint32_t vf[4][4];
            #pragma unroll
            for (int j = 0; j < 4; j++)
                ldsm_x4t(vf[j], sbV + vboff2[j] + ks * 16 * KSH * 2);
            #pragma unroll
            for (int nt = 0; nt < 8; nt++)
                mma_f16(o[nt][0], o[nt][1], o[nt][2], o[nt][3],
                        a[0], a[1], a[2], a[3],
                        vf[nt >> 1][(nt & 1) * 2], vf[nt >> 1][(nt & 1) * 2 + 1]);
        }
    }

    // ---- finalize ----
    l0 += __shfl_xor_sync(0xffffffffu, l0, 1);
    l0 += __shfl_xor_sync(0xffffffffu, l0, 2);
    l1 += __shfl_xor_sync(0xffffffffu, l1, 1);
    l1 += __shfl_xor_sync(0xffffffffu, l1, 2);
    const float inv0 = 1.f / l0;
    const float inv1 = 1.f / l1;

    __half* o0 = Og + ((size_t)(b * SEQ + q_row0)) * EMB + h * HD;
    __half* o1 = Og + ((size_t)(b * SEQ + q_row1)) * EMB + h * HD;
    #pragma unroll
    for (int nt = 0; nt < 8; nt++) {
        const int col = nt * 8 + 2 * tig;
        *(__half2*)(o0 + col) = __floats2half2_rn(o[nt][0] * inv0, o[nt][1] * inv0);
        *(__half2*)(o1 + col) = __floats2half2_rn(o[nt][2] * inv1, o[nt][3] * inv1);
    }
}

// ---------------- launch --------------------------------------------------------
extern "C" void kernel_launch(void* const* d_in, const int* in_sizes, int n_in,
                              void* d_out, int out_size)
{
    const float* x  = (const float*)d_in[0];
    const int*   am = (const int*)  d_in[1];
    const float* wq = (const float*)d_in[2];
    const float* wk = (const float*)d_in[3];
    const float* wv = (const float*)d_in[4];
    const float* wo = (const float*)d_in[5];
    float* out = (float*)d_out;

    __half *pxh, *pwh, *pq, *pk, *pv, *pao;
    cudaGetSymbolAddress((void**)&pxh, g_xh);
    cudaGetSymbolAddress((void**)&pwh, g_wh);
    cudaGetSymbolAddress((void**)&pq,  g_q);
    cudaGetSymbolAddress((void**)&pk,  g_k);
    cudaGetSymbolAddress((void**)&pv,  g_v);
    cudaGetSymbolAddress((void**)&pao, g_ao);

    // unconditional attribute sets (no static guards; host-side, capture-safe)
    cudaFuncSetAttribute(qkv_gemm, cudaFuncAttributeMaxDynamicSharedMemorySize, GSMEM_BYTES);
    cudaFuncSetAttribute(out_gemm, cudaFuncAttributeMaxDynamicSharedMemorySize, GSMEM_BYTES);
    cudaFuncSetAttribute(flash_tc, cudaFuncAttributeMaxDynamicSharedMemorySize, FLASH_SMEM_BYTES);

    cvt_x_kernel<<<2048, 256>>>((const float4*)x, (uint2*)pxh, MROWS * EMB / 4);
    cvt_w_kernel<<<dim3(256, 1, 4), 256>>>((const float4*)wq, (const float4*)wk,
                                           (const float4*)wv, (const float4*)wo,
                                           (uint2*)pwh);

    qkv_gemm<<<dim3(EMB / BN, MROWS / BM, 3), 256, GSMEM_BYTES>>>(pxh, pwh, pq, pk, pv);

    flash_tc<<<dim3(BATCH * NH, SEQ / 128), 256, FLASH_SMEM_BYTES>>>(pq, pk, pv, am, pao);

    out_gemm<<<dim3(EMB / BN, MROWS / BM), 256, GSMEM_BYTES>>>(pao, pwh + (size_t)3 * WSZ, out);
}